// round 11
// baseline (speedup 1.0000x reference)
#include <cuda_runtime.h>
#include <cuda_fp16.h>
#include <cstdint>

#define NC   3144   // counties
#define TT   156    // time steps
#define TP   154    // predicted steps (T - p)
#define TPAD 160    // padded t dimension
#define NNZ  31440
#define CAP  128    // bucket capacity (Poisson(10), max ~35)

#define NMT  99     // m-tiles of 32 for the transpose
#define K1_SCAT  123                    // ceil(NNZ/256)
#define K1_TRANS (NMT * 5)              // 495
#define K1_BASE  (13 * 20)              // 260: 13 m-groups x 20 t-chunks
#define K1_BLOCKS (K1_SCAT + K1_TRANS + K1_BASE)

// ---- scratch (zero-initialized at load; meta slots >= cnt stay zero) ----
__device__ int     g_count[NC];
__device__ int4    g_meta[NC * CAP];  // {row, bv, av, hv}; pad slots = 0
__device__ __half2 g_csdh[NC * TPAD]; // {cs, ds} fp16 at [m][t]

// ============================================================
// Kernel 1 (256 thr): scatter (123) + csdh transpose (495) +
// mobility/covariate base written DIRECTLY to out (260).
// ============================================================
__global__ void k1_kernel(
    const float* __restrict__ C, const float* __restrict__ D,
    const float* __restrict__ M, const float* __restrict__ cov,
    const float* __restrict__ mu, const float* __restrict__ nu,
    const float* __restrict__ ups, const float* __restrict__ zeta,
    const float* __restrict__ bnz, const float* __restrict__ anz,
    const float* __restrict__ hnz, const int* __restrict__ rows,
    const int* __restrict__ cols, float* __restrict__ out)
{
    const int b = blockIdx.x, tid = threadIdx.x;

    // ---------------- scatter ----------------
    if (b < K1_SCAT) {
        int k = b * 256 + tid;
        if (k < NNZ) {
            int c = cols[k];
            int slot = atomicAdd(&g_count[c], 1);
            if (slot < CAP)
                g_meta[c * CAP + slot] = make_int4(
                    rows[k], __float_as_int(bnz[k]),
                    __float_as_int(anz[k]), __float_as_int(hnz[k]));
        }
        return;
    }

    // ---------------- C/D lag-sum transpose -> fp16 [m][t] ----------------
    if (b < K1_SCAT + K1_TRANS) {
        __shared__ float sC[33][33], sD[33][33];
        const int tb = b - K1_SCAT;
        const int m0 = (tb % NMT) * 32, t0 = (tb / NMT) * 32;

        for (int idx = tid; idx < 33 * 32; idx += 256) {
            int r = idx >> 5, cm = idx & 31;
            int tg = min(t0 + r, TT - 1);
            int mg = min(m0 + cm, NC - 1);
            sC[r][cm] = C[tg * NC + mg];
            sD[r][cm] = D[tg * NC + mg];
        }
        __syncthreads();

        const int tx = tid & 31, ty = tid >> 5;   // tx = t offset
#pragma unroll
        for (int i = 0; i < 4; i++) {
            int ml = ty * 4 + i;
            int mg = m0 + ml;
            if (mg < NC) {
                float cs = sC[tx][ml] + sC[tx + 1][ml];
                float ds = sD[tx][ml] + sD[tx + 1][ml];
                g_csdh[mg * TPAD + t0 + tx] = __floats2half2_rn(cs, ds);
            }
        }
        return;
    }

    // ---------------- base: mobility + covariate -> out ----------------
    {
        const int bb = b - K1_SCAT - K1_TRANS;
        const int mgrp = bb % 13, chunk = bb / 13;
        const int m = mgrp * 256 + tid;
        if (m >= NC) return;
        const int t0 = chunk * 8;

        float cc = 0.f, cd = 0.f;
#pragma unroll
        for (int j = 0; j < 10; j++) {
            float cvv = cov[j * NC + m];
            cc += ups[j]  * cvv;
            cd += zeta[j] * cvv;
        }

        float muv[12], nuv[12];
#pragma unroll
        for (int i = 0; i < 12; i++) { muv[i] = mu[i]; nuv[i] = nu[i]; }

        float mn[6];
#pragma unroll
        for (int k = 0; k < 6; k++) mn[k] = M[(k * TT + t0) * NC + m];

#pragma unroll
        for (int j = 0; j < 8; j++) {
            int t = t0 + j;
            int tn = min(t + 1, TT - 1);
            float mc = cc, md = cd;
#pragma unroll
            for (int k = 0; k < 6; k++) {
                float v0 = mn[k];
                float v1 = M[(k * TT + tn) * NC + m];
                mn[k] = v1;
                mc += muv[k*2] * v0 + muv[k*2+1] * v1;
                md += nuv[k*2] * v0 + nuv[k*2+1] * v1;
            }
            if (t < TP) {
                out[t        * NC + m] = mc;
                out[(TP + t) * NC + m] = md;
            }
        }
    }
}

// ============================================================
// Kernel 2 (640 thr, 786 blocks): sparse gather, warp-task =
// (column, 32-t chunk) -> 15720 warps (~106/SM). Meta via
// warp-uniform 16B loads (L2-hot line shared by 5 warps).
// In-block smem transpose epilogue; coalesced RMW on out.
// ============================================================
__global__ void __launch_bounds__(640) k2_kernel(float* __restrict__ out)
{
    __shared__ float2 tile[TPAD][5];      // [t][m_local]

    const int tid  = threadIdx.x;
    const int wid  = tid >> 5, lane = tid & 31;
    const int cl   = wid / 5, chunk = wid - cl * 5;   // 4 cols x 5 chunks
    const int m0   = blockIdx.x * 4;
    const int m    = m0 + cl;             // NC = 786*4 exact
    const int toff = chunk * 32 + lane;

    const int cnt = g_count[m];           // warp-uniform
    const int jn  = min((cnt + 3) & ~3, 32);   // pad slots are zero-coef

    const int4* __restrict__ mp = &g_meta[m * CAP];
    const __half2* __restrict__ csd = g_csdh;

    float accC = 0.f, accD = 0.f;
    for (int j = 0; j < jn; j += 4) {
        int4 ma = mp[j], mb = mp[j + 1], mc_ = mp[j + 2], md_ = mp[j + 3];
        __half2 va = csd[ma.x  * TPAD + toff];
        __half2 vb = csd[mb.x  * TPAD + toff];
        __half2 vc = csd[mc_.x * TPAD + toff];
        __half2 vd = csd[md_.x * TPAD + toff];
        float2 pa = __half22float2(va);
        float2 pb = __half22float2(vb);
        float2 pc = __half22float2(vc);
        float2 pd = __half22float2(vd);
        accC += __int_as_float(ma.y)  * pa.x + __int_as_float(mb.y)  * pb.x
              + __int_as_float(mc_.y) * pc.x + __int_as_float(md_.y) * pd.x;
        accD += __int_as_float(ma.w)  * pa.x + __int_as_float(ma.z)  * pa.y
              + __int_as_float(mb.w)  * pb.x + __int_as_float(mb.z)  * pb.y
              + __int_as_float(mc_.w) * pc.x + __int_as_float(mc_.z) * pc.y
              + __int_as_float(md_.w) * pd.x + __int_as_float(md_.z) * pd.y;
    }
    for (int s = 32; s < cnt; s++) {      // rare tail (cnt > 32)
        int4 mm = mp[s];
        float2 p = __half22float2(csd[mm.x * TPAD + toff]);
        accC += __int_as_float(mm.y) * p.x;
        accD += __int_as_float(mm.w) * p.x + __int_as_float(mm.z) * p.y;
    }

    tile[toff][cl] = make_float2(accC, accD);
    __syncthreads();

    if (tid < 4) g_count[m0 + tid] = 0;   // re-arm (all reads done)

    // coalesced RMW: out already holds the base terms from k1
    if (tid < TP * 4) {
        int t = tid >> 2, mo = tid & 3;
        float2 v = tile[t][mo];
        out[t        * NC + m0 + mo] += v.x;
        out[(TP + t) * NC + m0 + mo] += v.y;
    }
}

// ============================================================
extern "C" void kernel_launch(void* const* d_in, const int* in_sizes, int n_in,
                              void* d_out, int out_size)
{
    const float* C    = (const float*)d_in[0];
    const float* D    = (const float*)d_in[1];
    const float* M    = (const float*)d_in[2];
    const float* cov  = (const float*)d_in[3];
    const float* bnz  = (const float*)d_in[4];
    const float* anz  = (const float*)d_in[5];
    const float* hnz  = (const float*)d_in[6];
    const float* mu   = (const float*)d_in[7];
    const float* nu   = (const float*)d_in[8];
    const float* ups  = (const float*)d_in[9];
    const float* zeta = (const float*)d_in[10];
    const int*   rows = (const int*)d_in[11];
    const int*   cols = (const int*)d_in[12];
    float* out = (float*)d_out;

    k1_kernel<<<K1_BLOCKS, 256>>>(C, D, M, cov, mu, nu, ups, zeta,
                                  bnz, anz, hnz, rows, cols, out);
    k2_kernel<<<NC / 4, 640>>>(out);
}

// round 12
// speedup vs baseline: 1.4679x; 1.4679x over previous
#include <cuda_runtime.h>
#include <cstdint>

#define NC   3144   // counties
#define TT   156    // time steps
#define TP   154    // predicted steps (T - p)
#define TPAD 160    // padded t dimension
#define NNZ  31440
#define CAP  128    // bucket capacity (Poisson(10), max ~35)

#define NMT  99     // m-tiles of 32 for the transpose
#define K1_SCAT  123                    // ceil(NNZ/256)
#define K1_TRANS (NMT * 5)              // 495
#define K1_BASE  (13 * 20)              // 260: 13 m-groups x 20 t-chunks
#define K1_BLOCKS (K1_SCAT + K1_TRANS + K1_BASE)

// ---- scratch (zero-initialized at load; meta slots >= cnt stay zero) ----
__device__ int    g_count[NC];
__device__ int4   g_meta[NC * CAP];   // {row, bv, av, hv}; pad slots = 0
__device__ float2 g_csd[NC * TPAD];   // {cs, ds} fp32 at [m][t]

// ============================================================
// Kernel 1 (256 thr): scatter (123) + csd transpose (495) +
// mobility/covariate base written DIRECTLY to out (260).
// ============================================================
__global__ void k1_kernel(
    const float* __restrict__ C, const float* __restrict__ D,
    const float* __restrict__ M, const float* __restrict__ cov,
    const float* __restrict__ mu, const float* __restrict__ nu,
    const float* __restrict__ ups, const float* __restrict__ zeta,
    const float* __restrict__ bnz, const float* __restrict__ anz,
    const float* __restrict__ hnz, const int* __restrict__ rows,
    const int* __restrict__ cols, float* __restrict__ out)
{
    const int b = blockIdx.x, tid = threadIdx.x;

    // ---------------- scatter ----------------
    if (b < K1_SCAT) {
        int k = b * 256 + tid;
        if (k < NNZ) {
            int c = cols[k];
            int slot = atomicAdd(&g_count[c], 1);
            if (slot < CAP)
                g_meta[c * CAP + slot] = make_int4(
                    rows[k], __float_as_int(bnz[k]),
                    __float_as_int(anz[k]), __float_as_int(hnz[k]));
        }
        return;
    }

    // ---------------- C/D lag-sum transpose -> fp32 [m][t] ----------------
    if (b < K1_SCAT + K1_TRANS) {
        __shared__ float sC[33][33], sD[33][33];
        const int tb = b - K1_SCAT;
        const int m0 = (tb % NMT) * 32, t0 = (tb / NMT) * 32;

        for (int idx = tid; idx < 33 * 32; idx += 256) {
            int r = idx >> 5, cm = idx & 31;
            int tg = min(t0 + r, TT - 1);
            int mg = min(m0 + cm, NC - 1);
            sC[r][cm] = C[tg * NC + mg];
            sD[r][cm] = D[tg * NC + mg];
        }
        __syncthreads();

        const int tx = tid & 31, ty = tid >> 5;   // tx = t offset
#pragma unroll
        for (int i = 0; i < 4; i++) {
            int ml = ty * 4 + i;
            int mg = m0 + ml;
            if (mg < NC) {
                float cs = sC[tx][ml] + sC[tx + 1][ml];
                float ds = sD[tx][ml] + sD[tx + 1][ml];
                g_csd[mg * TPAD + t0 + tx] = make_float2(cs, ds);
            }
        }
        return;
    }

    // ---------------- base: mobility + covariate -> out ----------------
    {
        const int bb = b - K1_SCAT - K1_TRANS;
        const int mgrp = bb % 13, chunk = bb / 13;
        const int m = mgrp * 256 + tid;
        if (m >= NC) return;
        const int t0 = chunk * 8;

        float cc = 0.f, cd = 0.f;
#pragma unroll
        for (int j = 0; j < 10; j++) {
            float cvv = cov[j * NC + m];
            cc += ups[j]  * cvv;
            cd += zeta[j] * cvv;
        }

        float muv[12], nuv[12];
#pragma unroll
        for (int i = 0; i < 12; i++) { muv[i] = mu[i]; nuv[i] = nu[i]; }

        float mn[6];
#pragma unroll
        for (int k = 0; k < 6; k++) mn[k] = M[(k * TT + t0) * NC + m];

#pragma unroll
        for (int j = 0; j < 8; j++) {
            int t = t0 + j;
            int tn = min(t + 1, TT - 1);
            float mc = cc, md = cd;
#pragma unroll
            for (int k = 0; k < 6; k++) {
                float v0 = mn[k];
                float v1 = M[(k * TT + tn) * NC + m];
                mn[k] = v1;
                mc += muv[k*2] * v0 + muv[k*2+1] * v1;
                md += nuv[k*2] * v0 + nuv[k*2+1] * v1;
            }
            if (t < TP) {
                out[t        * NC + m] = mc;
                out[(TP + t) * NC + m] = md;
            }
        }
    }
}

// ============================================================
// Kernel 2 (512 thr, 393 blocks): sparse gather.
// Warp-pair per column: warp covers all 160 t (5 float2 cells
// per lane) but only even/odd nnz slots -> serial chain halved.
// Meta staged in smem; epilogue sums both halves, RMW on out.
// ============================================================
__global__ void __launch_bounds__(512) k2_kernel(float* __restrict__ out)
{
    __shared__ int4   smeta[8][32];                 // 4 KB
    __shared__ int    scnt[8];
    __shared__ float2 tileA[TPAD][9], tileB[TPAD][9];   // 23 KB

    const int tid  = threadIdx.x;
    const int w    = tid >> 5, lane = tid & 31;
    const int col  = w >> 1, half = w & 1;
    const int m0   = blockIdx.x * 8;
    const int m    = m0 + col;            // NC = 393*8 exact

    // stage meta (coalesced: 512B per column) + counts
    if (tid < 256)
        smeta[tid >> 5][tid & 31] = g_meta[(m0 + (tid >> 5)) * CAP + (tid & 31)];
    if (tid < 8)
        scnt[tid] = g_count[m0 + tid];
    __syncthreads();
    if (tid < 8) g_count[m0 + tid] = 0;   // re-arm for graph replay

    const int cnt = scnt[col];
    const float2* __restrict__ csd = g_csd;

    float accC[5] = {0.f, 0.f, 0.f, 0.f, 0.f};
    float accD[5] = {0.f, 0.f, 0.f, 0.f, 0.f};

    int j = half;
    // batch two nnz per iteration (10 independent 256B loads)
    for (; j + 2 < cnt; j += 4) {
        int4 ma = smeta[col][j];
        int4 mb = smeta[col][j + 2];
        const float2* ra = &csd[ma.x * TPAD + lane];
        const float2* rb = &csd[mb.x * TPAD + lane];
        float2 va[5], vb[5];
#pragma unroll
        for (int i = 0; i < 5; i++) { va[i] = ra[32 * i]; vb[i] = rb[32 * i]; }
        float ba = __int_as_float(ma.y), aa = __int_as_float(ma.z), ha = __int_as_float(ma.w);
        float bb = __int_as_float(mb.y), ab = __int_as_float(mb.z), hb = __int_as_float(mb.w);
#pragma unroll
        for (int i = 0; i < 5; i++) {
            accC[i] += ba * va[i].x + bb * vb[i].x;
            accD[i] += ha * va[i].x + aa * va[i].y
                     + hb * vb[i].x + ab * vb[i].y;
        }
    }
    for (; j < cnt; j += 2) {
        int4 md = (j < 32) ? smeta[col][j] : g_meta[m * CAP + j];
        const float2* rr = &csd[md.x * TPAD + lane];
        float bv = __int_as_float(md.y);
        float av = __int_as_float(md.z);
        float hv = __int_as_float(md.w);
#pragma unroll
        for (int i = 0; i < 5; i++) {
            float2 v = rr[32 * i];
            accC[i] += bv * v.x;
            accD[i] += hv * v.x + av * v.y;
        }
    }

    // each half writes its own tile
    if (half == 0) {
#pragma unroll
        for (int i = 0; i < 5; i++)
            tileA[lane + 32 * i][col] = make_float2(accC[i], accD[i]);
    } else {
#pragma unroll
        for (int i = 0; i < 5; i++)
            tileB[lane + 32 * i][col] = make_float2(accC[i], accD[i]);
    }
    __syncthreads();

    // coalesced RMW: out already holds the base terms from k1
#pragma unroll
    for (int i = 0; i < 5; i++) {
        int idx = tid + i * 512;          // < 2560
        int t = idx >> 3, mo = idx & 7;
        if (t < TP) {
            float2 a = tileA[t][mo], bvv = tileB[t][mo];
            out[t        * NC + m0 + mo] += a.x + bvv.x;
            out[(TP + t) * NC + m0 + mo] += a.y + bvv.y;
        }
    }
}

// ============================================================
extern "C" void kernel_launch(void* const* d_in, const int* in_sizes, int n_in,
                              void* d_out, int out_size)
{
    const float* C    = (const float*)d_in[0];
    const float* D    = (const float*)d_in[1];
    const float* M    = (const float*)d_in[2];
    const float* cov  = (const float*)d_in[3];
    const float* bnz  = (const float*)d_in[4];
    const float* anz  = (const float*)d_in[5];
    const float* hnz  = (const float*)d_in[6];
    const float* mu   = (const float*)d_in[7];
    const float* nu   = (const float*)d_in[8];
    const float* ups  = (const float*)d_in[9];
    const float* zeta = (const float*)d_in[10];
    const int*   rows = (const int*)d_in[11];
    const int*   cols = (const int*)d_in[12];
    float* out = (float*)d_out;

    k1_kernel<<<K1_BLOCKS, 256>>>(C, D, M, cov, mu, nu, ups, zeta,
                                  bnz, anz, hnz, rows, cols, out);
    k2_kernel<<<NC / 8, 512>>>(out);
}

// round 14
// speedup vs baseline: 1.6447x; 1.1204x over previous
#include <cuda_runtime.h>
#include <cstdint>

#define NC   3144   // counties
#define TT   156    // time steps
#define TP   154    // predicted steps (T - p)
#define TPAD 160    // padded t dimension
#define NNZ  31440
#define CAP  128    // bucket capacity (Poisson(10), max ~35)

#define NMT  99     // m-tiles of 32 for the transpose
#define KA_SCAT  123                    // ceil(NNZ/256)
#define KA_TRANS (NMT * 5)              // 495
#define KA_COV   13                     // ceil(NC/256)
#define KA_BLOCKS (KA_SCAT + KA_TRANS + KA_COV)

#define GATH_BLOCKS 393                 // NC/8
#define BASE_BLOCKS 260                 // 13 m-groups x 20 t-chunks
#define KBC_BLOCKS  (GATH_BLOCKS + BASE_BLOCKS)

// ---- scratch (zero-initialized at load; meta slots >= cnt stay zero) ----
__device__ int    g_count[NC];
__device__ int4   g_meta[NC * CAP];   // {row, bv, av, hv}; pad slots = 0
__device__ float2 g_csd[NC * TPAD];   // {cs, ds} fp32 at [m][t]
__device__ float2 g_covb[NC];         // {ups@cov, zeta@cov}
__device__ float  g_gth[2 * TP * NC]; // gather result, out layout

// ============================================================
// Kernel A (256 thr): scatter (123) + csd transpose (495) +
// covariate base (13).
// ============================================================
__global__ void kA_kernel(
    const float* __restrict__ C, const float* __restrict__ D,
    const float* __restrict__ cov,
    const float* __restrict__ ups, const float* __restrict__ zeta,
    const float* __restrict__ bnz, const float* __restrict__ anz,
    const float* __restrict__ hnz, const int* __restrict__ rows,
    const int* __restrict__ cols)
{
    const int b = blockIdx.x, tid = threadIdx.x;

    if (b < KA_SCAT) {
        int k = b * 256 + tid;
        if (k < NNZ) {
            int c = cols[k];
            int slot = atomicAdd(&g_count[c], 1);
            if (slot < CAP)
                g_meta[c * CAP + slot] = make_int4(
                    rows[k], __float_as_int(bnz[k]),
                    __float_as_int(anz[k]), __float_as_int(hnz[k]));
        }
        return;
    }

    if (b < KA_SCAT + KA_TRANS) {
        __shared__ float sC[33][33], sD[33][33];
        const int tb = b - KA_SCAT;
        const int m0 = (tb % NMT) * 32, t0 = (tb / NMT) * 32;

        for (int idx = tid; idx < 33 * 32; idx += 256) {
            int r = idx >> 5, cm = idx & 31;
            int tg = min(t0 + r, TT - 1);
            int mg = min(m0 + cm, NC - 1);
            sC[r][cm] = C[tg * NC + mg];
            sD[r][cm] = D[tg * NC + mg];
        }
        __syncthreads();

        const int tx = tid & 31, ty = tid >> 5;   // tx = t offset
#pragma unroll
        for (int i = 0; i < 4; i++) {
            int ml = ty * 4 + i;
            int mg = m0 + ml;
            if (mg < NC) {
                float cs = sC[tx][ml] + sC[tx + 1][ml];
                float ds = sD[tx][ml] + sD[tx + 1][ml];
                g_csd[mg * TPAD + t0 + tx] = make_float2(cs, ds);
            }
        }
        return;
    }

    {   // covariate dot products
        int m = (b - KA_SCAT - KA_TRANS) * 256 + tid;
        if (m < NC) {
            float a = 0.f, z = 0.f;
#pragma unroll
            for (int j = 0; j < 10; j++) {
                float cvv = cov[j * NC + m];
                a += ups[j]  * cvv;
                z += zeta[j] * cvv;
            }
            g_covb[m] = make_float2(a, z);
        }
    }
}

// ============================================================
// Kernel BC (256 thr, 653 blocks): FUSED gather + base.
// Blocks 0..392: sparse gather (R4 shape) -> g_gth.
// Blocks 393..652: mobility + covariate base -> out.
// Both families co-schedule: base fills the issue slots the
// latency-bound gather leaves idle.
// ============================================================
__global__ void __launch_bounds__(256) kBC_kernel(
    const float* __restrict__ M, const float* __restrict__ mu,
    const float* __restrict__ nu, float* __restrict__ out)
{
    const int tid = threadIdx.x;

    if (blockIdx.x < GATH_BLOCKS) {
        // ---------------- sparse gather ----------------
        __shared__ int4   smeta[8][32];
        __shared__ int    scnt[8];
        __shared__ float2 tile[TPAD][9];      // [t][m_local], padded

        const int w    = tid >> 5, lane = tid & 31;
        const int m0   = blockIdx.x * 8;
        const int m    = m0 + w;              // NC = 393*8 exact

        smeta[tid >> 5][tid & 31] = g_meta[(m0 + (tid >> 5)) * CAP + (tid & 31)];
        if (tid < 8) scnt[tid] = g_count[m0 + tid];
        __syncthreads();
        if (tid < 8) g_count[m0 + tid] = 0;   // re-arm for graph replay

        const int cnt = scnt[w];
        const float2* __restrict__ csd = g_csd;

        float accC[5] = {0.f, 0.f, 0.f, 0.f, 0.f};
        float accD[5] = {0.f, 0.f, 0.f, 0.f, 0.f};

        const int jn = min(cnt, 32);
#pragma unroll 2
        for (int j = 0; j < jn; j++) {
            int4 md = smeta[w][j];            // LDS broadcast
            const float2* __restrict__ cr = &csd[md.x * TPAD + lane];
            float bv = __int_as_float(md.y);
            float av = __int_as_float(md.z);
            float hv = __int_as_float(md.w);
            float2 v0 = cr[0], v1 = cr[32], v2 = cr[64], v3 = cr[96], v4 = cr[128];
            accC[0] += bv * v0.x;  accD[0] += hv * v0.x + av * v0.y;
            accC[1] += bv * v1.x;  accD[1] += hv * v1.x + av * v1.y;
            accC[2] += bv * v2.x;  accD[2] += hv * v2.x + av * v2.y;
            accC[3] += bv * v3.x;  accD[3] += hv * v3.x + av * v3.y;
            accC[4] += bv * v4.x;  accD[4] += hv * v4.x + av * v4.y;
        }
        for (int s = 32; s < cnt; s++) {      // rare tail
            int4 md = g_meta[m * CAP + s];
            const float2* __restrict__ cr = &csd[md.x * TPAD + lane];
            float bv = __int_as_float(md.y);
            float av = __int_as_float(md.z);
            float hv = __int_as_float(md.w);
#pragma unroll
            for (int i = 0; i < 5; i++) {
                float2 v = cr[32 * i];
                accC[i] += bv * v.x;
                accD[i] += hv * v.x + av * v.y;
            }
        }

#pragma unroll
        for (int i = 0; i < 5; i++)
            tile[lane + 32 * i][w] = make_float2(accC[i], accD[i]);
        __syncthreads();

#pragma unroll
        for (int i = 0; i < 10; i++) {
            int idx = tid + i * 256;          // < 2560
            int t = idx >> 3, mo = idx & 7;
            if (t < TP) {
                float2 v = tile[t][mo];
                g_gth[t        * NC + m0 + mo] = v.x;
                g_gth[(TP + t) * NC + m0 + mo] = v.y;
            }
        }
    } else {
        // ---------------- mobility + covariate base ----------------
        const int bb = blockIdx.x - GATH_BLOCKS;
        const int mgrp = bb % 13, chunk = bb / 13;
        const int m = mgrp * 256 + tid;
        if (m >= NC) return;
        const int t0 = chunk * 8;

        float2 cvb = g_covb[m];
        float muv[12], nuv[12];
#pragma unroll
        for (int i = 0; i < 12; i++) { muv[i] = mu[i]; nuv[i] = nu[i]; }

        float mn[6];
#pragma unroll
        for (int k = 0; k < 6; k++) mn[k] = M[(k * TT + t0) * NC + m];

#pragma unroll
        for (int j = 0; j < 8; j++) {
            int t = t0 + j;
            int tn = min(t + 1, TT - 1);
            float mc = cvb.x, md = cvb.y;
#pragma unroll
            for (int k = 0; k < 6; k++) {
                float v0 = mn[k];
                float v1 = M[(k * TT + tn) * NC + m];
                mn[k] = v1;
                mc += muv[k*2] * v0 + muv[k*2+1] * v1;
                md += nuv[k*2] * v0 + nuv[k*2+1] * v1;
            }
            if (t < TP) {
                out[t        * NC + m] = mc;
                out[(TP + t) * NC + m] = md;
            }
        }
    }
}

// ============================================================
// Kernel D: join — out += gather. float4 over 968352 floats.
// ============================================================
__global__ void kD_kernel(float* __restrict__ out)
{
    int idx = blockIdx.x * 256 + threadIdx.x;
    if (idx < (2 * TP * NC) / 4) {
        float4 o = reinterpret_cast<float4*>(out)[idx];
        float4 g = reinterpret_cast<const float4*>(g_gth)[idx];
        o.x += g.x; o.y += g.y; o.z += g.z; o.w += g.w;
        reinterpret_cast<float4*>(out)[idx] = o;
    }
}

// ============================================================
extern "C" void kernel_launch(void* const* d_in, const int* in_sizes, int n_in,
                              void* d_out, int out_size)
{
    const float* C    = (const float*)d_in[0];
    const float* D    = (const float*)d_in[1];
    const float* M    = (const float*)d_in[2];
    const float* cov  = (const float*)d_in[3];
    const float* bnz  = (const float*)d_in[4];
    const float* anz  = (const float*)d_in[5];
    const float* hnz  = (const float*)d_in[6];
    const float* mu   = (const float*)d_in[7];
    const float* nu   = (const float*)d_in[8];
    const float* ups  = (const float*)d_in[9];
    const float* zeta = (const float*)d_in[10];
    const int*   rows = (const int*)d_in[11];
    const int*   cols = (const int*)d_in[12];
    float* out = (float*)d_out;

    kA_kernel<<<KA_BLOCKS, 256>>>(C, D, cov, ups, zeta,
                                  bnz, anz, hnz, rows, cols);
    kBC_kernel<<<KBC_BLOCKS, 256>>>(M, mu, nu, out);
    kD_kernel<<<(2 * TP * NC / 4 + 255) / 256, 256>>>(out);
}